// round 6
// baseline (speedup 1.0000x reference)
#include <cuda_runtime.h>
#include <math.h>

#define S_ROWS 16384
#define N_COLS 4096
#define DIMK   512

// -------- scratch (static device allocations are allowed) --------
static __device__ float  g_zimg[S_ROWS * DIMK];   // normalized image embeddings (aligned copy)
static __device__ float  g_ztxt[N_COLS * DIMK];   // normalized text embeddings  (aligned copy)
static __device__ float  g_loss[S_ROWS];          // potential_positive_losses
static __device__ int    g_segmin[N_COLS];        // float-bits min loss per key
static __device__ int    g_sel[N_COLS];           // selected image index per key (S_ROWS = none)
static __device__ double g_sum;                   // final loss accumulator

// -------- init --------
__global__ void k_init() {
    int i = blockIdx.x * blockDim.x + threadIdx.x;
    if (i < N_COLS) { g_segmin[i] = 0x7F800000; g_sel[i] = S_ROWS; }
    if (i == 0) g_sum = 0.0;
}

// -------- row L2 normalize: writes aligned scratch + (misaligned) d_out region --------
__global__ void k_normalize(const float* __restrict__ in, float* __restrict__ aligned,
                            float* __restrict__ outreg, int rows) {
    int w    = (blockIdx.x * blockDim.x + threadIdx.x) >> 5;
    int lane = threadIdx.x & 31;
    if (w >= rows) return;
    const float4* src = (const float4*)(in + (size_t)w * DIMK);
    float4 v[4];
    float ss = 0.f;
#pragma unroll
    for (int c = 0; c < 4; c++) {
        v[c] = src[c * 32 + lane];
        ss += v[c].x * v[c].x + v[c].y * v[c].y + v[c].z * v[c].z + v[c].w * v[c].w;
    }
#pragma unroll
    for (int o = 16; o; o >>= 1) ss += __shfl_xor_sync(0xffffffffu, ss, o);
    float scale = 1.0f / (sqrtf(ss) + 1e-12f);
    float4* dst = (float4*)(aligned + (size_t)w * DIMK);
    float*  dr  = outreg + (size_t)w * DIMK;
#pragma unroll
    for (int c = 0; c < 4; c++) {
        float4 o4 = make_float4(v[c].x * scale, v[c].y * scale, v[c].z * scale, v[c].w * scale);
        dst[c * 32 + lane] = o4;
        int base = (c * 32 + lane) * 4;
        dr[base + 0] = o4.x; dr[base + 1] = o4.y; dr[base + 2] = o4.z; dr[base + 3] = o4.w;
    }
}

// -------- tiled NT GEMM: C[M,Ncols] = (A or A[gather]) * B^T * t + bias --------
// BM=BN=128, BK=16, 256 threads, 8x8 micro-tile (2x2 quadrants of float4)
__global__ __launch_bounds__(256) void k_gemm_nt(
    const float* __restrict__ A, const float* __restrict__ B, float* __restrict__ C,
    int Ncols, const int* __restrict__ gather,
    const float* __restrict__ logt_p, const float* __restrict__ bias_p)
{
    __shared__ float As[16 * 132];
    __shared__ float Bs[16 * 132];

    const int tid = threadIdx.x;
    const int bx  = blockIdx.x;   // N tile
    const int by  = blockIdx.y;   // M tile
    const int tx  = tid & 15;
    const int ty  = tid >> 4;
    const int tx4 = tx * 4;
    const int ty4 = ty * 4;

    // tile-load mapping: each thread loads 2 float4 from A, 2 from B per k-tile
    const int rowL0 = tid >> 2;        // 0..63
    const int rowL1 = rowL0 + 64;      // 64..127
    const int cL    = (tid & 3) * 4;   // k-offset within 16

    const float* ap0; const float* ap1;
    bool z0 = false, z1 = false;
    {
        int gr0 = by * 128 + rowL0;
        int gr1 = by * 128 + rowL1;
        if (gather) {
            int g0 = gather[gr0], g1 = gather[gr1];
            z0 = (g0 >= S_ROWS); z1 = (g1 >= S_ROWS);
            ap0 = A + (size_t)(z0 ? 0 : g0) * DIMK + cL;
            ap1 = A + (size_t)(z1 ? 0 : g1) * DIMK + cL;
        } else {
            ap0 = A + (size_t)gr0 * DIMK + cL;
            ap1 = A + (size_t)gr1 * DIMK + cL;
        }
    }
    const float* bp0 = B + (size_t)(bx * 128 + rowL0) * DIMK + cL;
    const float* bp1 = B + (size_t)(bx * 128 + rowL1) * DIMK + cL;

    float acc[8][8];
#pragma unroll
    for (int i = 0; i < 8; i++)
#pragma unroll
        for (int j = 0; j < 8; j++) acc[i][j] = 0.f;

    for (int kt = 0; kt < DIMK; kt += 16) {
        float4 a0 = z0 ? make_float4(0.f, 0.f, 0.f, 0.f) : *(const float4*)(ap0 + kt);
        float4 a1 = z1 ? make_float4(0.f, 0.f, 0.f, 0.f) : *(const float4*)(ap1 + kt);
        float4 b0 = *(const float4*)(bp0 + kt);
        float4 b1 = *(const float4*)(bp1 + kt);

        __syncthreads();
        As[(cL + 0) * 132 + rowL0] = a0.x;
        As[(cL + 1) * 132 + rowL0] = a0.y;
        As[(cL + 2) * 132 + rowL0] = a0.z;
        As[(cL + 3) * 132 + rowL0] = a0.w;
        As[(cL + 0) * 132 + rowL1] = a1.x;
        As[(cL + 1) * 132 + rowL1] = a1.y;
        As[(cL + 2) * 132 + rowL1] = a1.z;
        As[(cL + 3) * 132 + rowL1] = a1.w;
        Bs[(cL + 0) * 132 + rowL0] = b0.x;
        Bs[(cL + 1) * 132 + rowL0] = b0.y;
        Bs[(cL + 2) * 132 + rowL0] = b0.z;
        Bs[(cL + 3) * 132 + rowL0] = b0.w;
        Bs[(cL + 0) * 132 + rowL1] = b1.x;
        Bs[(cL + 1) * 132 + rowL1] = b1.y;
        Bs[(cL + 2) * 132 + rowL1] = b1.z;
        Bs[(cL + 3) * 132 + rowL1] = b1.w;
        __syncthreads();

#pragma unroll
        for (int k = 0; k < 16; k++) {
            float4 xa0 = *(const float4*)&As[k * 132 + ty4];
            float4 xa1 = *(const float4*)&As[k * 132 + ty4 + 64];
            float4 xb0 = *(const float4*)&Bs[k * 132 + tx4];
            float4 xb1 = *(const float4*)&Bs[k * 132 + tx4 + 64];
            float a[8] = {xa0.x, xa0.y, xa0.z, xa0.w, xa1.x, xa1.y, xa1.z, xa1.w};
            float b[8] = {xb0.x, xb0.y, xb0.z, xb0.w, xb1.x, xb1.y, xb1.z, xb1.w};
#pragma unroll
            for (int i = 0; i < 8; i++)
#pragma unroll
                for (int j = 0; j < 8; j++) acc[i][j] += a[i] * b[j];
        }
    }

    const float t  = expf(*logt_p);
    const float bs = *bias_p;
#pragma unroll
    for (int qi = 0; qi < 2; qi++)
#pragma unroll
        for (int i = 0; i < 4; i++) {
            size_t r = (size_t)(by * 128 + qi * 64 + ty4 + i);
            float* crow = C + r * (size_t)Ncols + (size_t)(bx * 128);
#pragma unroll
            for (int qj = 0; qj < 2; qj++)
#pragma unroll
                for (int j = 0; j < 4; j++)
                    crow[qj * 64 + tx4 + j] = acc[qi * 4 + i][qj * 4 + j] * t + bs;
        }
}

// -------- true-positive losses (fp64 dot for tie robustness) + segment min --------
__global__ void k_tploss(const int* __restrict__ key,
                         const float* __restrict__ logt_p, const float* __restrict__ bias_p) {
    int s    = blockIdx.x * (blockDim.x >> 5) + (threadIdx.x >> 5);
    int lane = threadIdx.x & 31;
    if (s >= S_ROWS) return;
    int k = key[s];
    const float4* a = (const float4*)(g_zimg + (size_t)s * DIMK);
    const float4* b = (const float4*)(g_ztxt + (size_t)k * DIMK);
    double acc = 0.0;
#pragma unroll
    for (int c = 0; c < 4; c++) {
        float4 av = a[c * 32 + lane];
        float4 bv = b[c * 32 + lane];
        acc += (double)av.x * bv.x + (double)av.y * bv.y +
               (double)av.z * bv.z + (double)av.w * bv.w;
    }
#pragma unroll
    for (int o = 16; o; o >>= 1) acc += __shfl_xor_sync(0xffffffffu, acc, o);
    if (lane == 0) {
        float t = expf(*logt_p), bs = *bias_p;
        float logit = (float)acc * t + bs;
        float y = -logit;
        float loss = fmaxf(y, 0.f) + log1pf(expf(-fabsf(y)));  // softplus(-logit)
        g_loss[s] = loss;
        atomicMin(&g_segmin[k], __float_as_int(loss));  // loss > 0 -> int order == float order
    }
}

// -------- pick smallest index among losses equal to segment min --------
__global__ void k_select(const int* __restrict__ key) {
    int s = blockIdx.x * blockDim.x + threadIdx.x;
    if (s >= S_ROWS) return;
    int k = key[s];
    if (__float_as_int(g_loss[s]) == g_segmin[k]) atomicMin(&g_sel[k], s);
}

__global__ void k_writesel(float* __restrict__ outsel) {
    int n = blockIdx.x * blockDim.x + threadIdx.x;
    if (n < N_COLS) {
        int v = g_sel[n];
        outsel[n] = (v < S_ROWS) ? (float)v : -1.0f;
    }
}

// -------- final loss reduction over final_logits --------
__global__ void k_losssum(const float* __restrict__ FL) {
    const size_t NN = (size_t)N_COLS * N_COLS;
    size_t idx    = (size_t)blockIdx.x * blockDim.x + threadIdx.x;
    size_t stride = (size_t)gridDim.x * blockDim.x;
    double local = 0.0;
    for (; idx < NN; idx += stride) {
        int i = (int)(idx >> 12);
        int j = (int)(idx & (N_COLS - 1));
        float logit = FL[idx];
        float x = (i == j) ? -logit : logit;             // -(label * logit)
        local += (double)(fmaxf(x, 0.f) + log1pf(expf(-fabsf(x))));
    }
    __shared__ double sm[256];
    sm[threadIdx.x] = local;
    __syncthreads();
    for (int o = 128; o; o >>= 1) {
        if (threadIdx.x < o) sm[threadIdx.x] += sm[threadIdx.x + o];
        __syncthreads();
    }
    if (threadIdx.x == 0) atomicAdd(&g_sum, sm[0]);
}

__global__ void k_writeloss(float* __restrict__ out0) {
    if (threadIdx.x == 0) out0[0] = (float)(g_sum / (double)N_COLS);
}

// -------- launcher --------
extern "C" void kernel_launch(void* const* d_in, const int* in_sizes, int n_in,
                              void* d_out, int out_size) {
    const float* img  = (const float*)d_in[0];
    const float* txt  = (const float*)d_in[1];
    const int*   key  = (const int*)d_in[2];
    const float* logt = (const float*)d_in[3];
    const float* bias = (const float*)d_in[4];
    float* out = (float*)d_out;

    // output layout (floats): [loss:1][sel:4096][zimg:S*512][ztxt:N*512][all_pairs:S*N][final:N*N]
    float* out_sel  = out + 1;
    float* out_zimg = out + 1 + N_COLS;
    float* out_ztxt = out_zimg + (size_t)S_ROWS * DIMK;
    float* out_ap   = out_ztxt + (size_t)N_COLS * DIMK;
    float* out_fl   = out_ap + (size_t)S_ROWS * N_COLS;

    void *p_zimg, *p_ztxt, *p_sel;
    cudaGetSymbolAddress(&p_zimg, g_zimg);
    cudaGetSymbolAddress(&p_ztxt, g_ztxt);
    cudaGetSymbolAddress(&p_sel,  g_sel);

    k_init<<<(N_COLS + 255) / 256, 256>>>();

    k_normalize<<<(S_ROWS * 32 + 255) / 256, 256>>>(img, (float*)p_zimg, out_zimg, S_ROWS);
    k_normalize<<<(N_COLS * 32 + 255) / 256, 256>>>(txt, (float*)p_ztxt, out_ztxt, N_COLS);

    // all_pairs_logits [S, N]
    {
        dim3 grid(N_COLS / 128, S_ROWS / 128);
        k_gemm_nt<<<grid, 256>>>((const float*)p_zimg, (const float*)p_ztxt, out_ap,
                                 N_COLS, nullptr, logt, bias);
    }

    k_tploss<<<(S_ROWS + 7) / 8, 256>>>(key, logt, bias);
    k_select<<<(S_ROWS + 255) / 256, 256>>>(key);
    k_writesel<<<(N_COLS + 255) / 256, 256>>>(out_sel);

    // final_logits_matrix [N, N] with gathered/zeroed rows
    {
        dim3 grid(N_COLS / 128, N_COLS / 128);
        k_gemm_nt<<<grid, 256>>>((const float*)p_zimg, (const float*)p_ztxt, out_fl,
                                 N_COLS, (const int*)p_sel, logt, bias);
    }

    k_losssum<<<2048, 256>>>(out_fl);
    k_writeloss<<<1, 32>>>(out + 0);
}

// round 9
// speedup vs baseline: 3.2014x; 3.2014x over previous
#include <cuda_runtime.h>
#include <math.h>
#include <stdint.h>

#define S_ROWS 16384
#define N_COLS 4096
#define DIMK   512
#define KSLABS 16            // 512 / 32
#define STAGE_BYTES 98304u   // A(hi+lo) 32KB + B(hi+lo) 64KB

// ---------------- static device scratch ----------------
static __device__ float  g_zimg[S_ROWS * DIMK];
static __device__ float  g_ztxt[N_COLS * DIMK];
// blocked tf32-split operand images (pre-swizzled SMEM tile layout)
// A bands: 128 rows; per (band,slab): [hi 16KB][lo 16KB] = 8192 floats
// B bands: 256 rows; per (band,slab): [hi 32KB][lo 32KB] = 16384 floats
static __device__ float  g_A1[(size_t)S_ROWS * 2 * DIMK];
static __device__ float  g_B [(size_t)N_COLS * 2 * DIMK];
static __device__ float  g_A2[(size_t)N_COLS * 2 * DIMK];
static __device__ float  g_loss[S_ROWS];
static __device__ int    g_segmin[N_COLS];
static __device__ int    g_sel[N_COLS];
static __device__ double g_sum;

// ---------------- small helpers ----------------
__device__ __forceinline__ uint32_t swz128(uint32_t o) { return o ^ ((o >> 3) & 0x70); }

__device__ __forceinline__ uint32_t smem_u32(const void* p) {
    uint32_t a;
    asm("{ .reg .u64 t; cvta.to.shared.u64 t, %1; cvt.u32.u64 %0, t; }" : "=r"(a) : "l"(p));
    return a;
}

__device__ __forceinline__ void tf32split(float x, float& h, float& l) {
    uint32_t hb; asm("cvt.rna.tf32.f32 %0, %1;" : "=r"(hb) : "f"(x));
    h = __uint_as_float(hb);
    float r = x - h;
    uint32_t lb; asm("cvt.rna.tf32.f32 %0, %1;" : "=r"(lb) : "f"(r));
    l = __uint_as_float(lb);
}

// ---------------- init ----------------
__global__ void k_init() {
    int i = blockIdx.x * blockDim.x + threadIdx.x;
    if (i < N_COLS) { g_segmin[i] = 0x7F800000; g_sel[i] = S_ROWS; }
    if (i == 0) g_sum = 0.0;
}

// ---------------- row L2 normalize ----------------
__global__ void k_normalize(const float* __restrict__ in, float* __restrict__ aligned,
                            float* __restrict__ outreg, int rows) {
    int w    = (blockIdx.x * blockDim.x + threadIdx.x) >> 5;
    int lane = threadIdx.x & 31;
    if (w >= rows) return;
    const float4* src = (const float4*)(in + (size_t)w * DIMK);
    float4 v[4];
    float ss = 0.f;
#pragma unroll
    for (int c = 0; c < 4; c++) {
        v[c] = src[c * 32 + lane];
        ss += v[c].x * v[c].x + v[c].y * v[c].y + v[c].z * v[c].z + v[c].w * v[c].w;
    }
#pragma unroll
    for (int o = 16; o; o >>= 1) ss += __shfl_xor_sync(0xffffffffu, ss, o);
    float scale = 1.0f / (sqrtf(ss) + 1e-12f);
    float4* dst = (float4*)(aligned + (size_t)w * DIMK);
    float*  dr  = outreg + (size_t)w * DIMK;
#pragma unroll
    for (int c = 0; c < 4; c++) {
        float4 o4 = make_float4(v[c].x * scale, v[c].y * scale, v[c].z * scale, v[c].w * scale);
        dst[c * 32 + lane] = o4;
        int base = (c * 32 + lane) * 4;
        dr[base + 0] = o4.x; dr[base + 1] = o4.y; dr[base + 2] = o4.z; dr[base + 3] = o4.w;
    }
}

// ---------------- pack: fp32 rows -> blocked tf32-split swizzled tile images ----------------
// band_log2 = 7 for A (128-row bands), 8 for B (256-row bands)
__global__ void k_pack(const float* __restrict__ src, float* __restrict__ dst,
                       int rows, int band_log2, const int* __restrict__ gather) {
    int idx = blockIdx.x * blockDim.x + threadIdx.x;     // one float4 per thread
    if (idx >= rows * 128) return;
    int row = idx >> 7, q = idx & 127;
    int slab = q >> 3, kq = q & 7;

    int srow = row; bool zero = false;
    if (gather) {
        int g = gather[row];
        if (g >= S_ROWS) { zero = true; srow = 0; } else srow = g;
    }
    float4 v = zero ? make_float4(0.f, 0.f, 0.f, 0.f)
                    : ((const float4*)(src + (size_t)srow * DIMK))[q];
    float4 h4, l4;
    tf32split(v.x, h4.x, l4.x); tf32split(v.y, h4.y, l4.y);
    tf32split(v.z, h4.z, l4.z); tf32split(v.w, h4.w, l4.w);

    int band = row >> band_log2;
    int lr   = row & ((1 << band_log2) - 1);
    size_t pair_floats = (size_t)(1 << band_log2) * 64;   // rows*32*2
    size_t base = ((size_t)band * KSLABS + slab) * pair_floats;
    uint32_t off = swz128((uint32_t)lr * 128 + (uint32_t)kq * 16) >> 2;

    *(float4*)(dst + base + off)                   = h4;
    *(float4*)(dst + base + pair_floats / 2 + off) = l4;
}

// ---------------- tcgen05 TF32 GEMM (3xTF32), tile M128 x N256, K=512 ----------------
// idesc: dtype F32 (bits4:5=1), atype/btype TF32 (=2), N=256, M=128
static constexpr uint32_t IDESC_TF32 =
    (1u << 4) | (2u << 7) | (2u << 10) | ((256u >> 3) << 17) | ((128u >> 4) << 24);

static constexpr uint64_t DESC_BASE_SW128 =
    (uint64_t(2) << 61) | (uint64_t(1) << 46) | (uint64_t(64) << 32) | (uint64_t(1) << 16);
__device__ __forceinline__ uint64_t mkdesc(uint32_t smem_addr) {
    return DESC_BASE_SW128 | ((uint64_t)(smem_addr >> 4) & 0x3FFF);
}

#if defined(__CUDA_ARCH_FEAT_SM103_ALL) || defined(__CUDA_ARCH_FEAT_SM100_ALL)
#define HAS_TCGEN05 1
#else
#define HAS_TCGEN05 0
#endif

#if HAS_TCGEN05
__device__ __forceinline__ void mma_tf32(uint32_t d, uint64_t ad, uint64_t bd, uint32_t en) {
    asm volatile(
        "{\n\t.reg .pred p;\n\t"
        "setp.ne.u32 p, %4, 0;\n\t"
        "tcgen05.mma.cta_group::1.kind::tf32 [%0], %1, %2, %3, {%5, %5, %5, %5}, p;\n\t}"
        :: "r"(d), "l"(ad), "l"(bd), "r"(IDESC_TF32), "r"(en), "r"(0u) : "memory");
}
__device__ __forceinline__ void tc_commit(uint32_t mbar) {
    asm volatile(
        "tcgen05.commit.cta_group::1.mbarrier::arrive::one.shared::cluster.b64 [%0];"
        :: "r"(mbar) : "memory");
}
#endif

__device__ __forceinline__ void bulk_copy(uint32_t dst, const void* src, uint32_t bytes, uint32_t mbar) {
    asm volatile(
        "cp.async.bulk.shared::cluster.global.mbarrier::complete_tx::bytes [%0], [%1], %2, [%3];"
        :: "r"(dst), "l"(src), "r"(bytes), "r"(mbar) : "memory");
}
__device__ __forceinline__ void mbar_init(uint32_t mbar, uint32_t cnt) {
    asm volatile("mbarrier.init.shared.b64 [%0], %1;" :: "r"(mbar), "r"(cnt) : "memory");
}
__device__ __forceinline__ void mbar_expect(uint32_t mbar, uint32_t bytes) {
    asm volatile("mbarrier.arrive.expect_tx.shared.b64 _, [%0], %1;" :: "r"(mbar), "r"(bytes) : "memory");
}
__device__ __forceinline__ void mbar_wait(uint32_t mbar, uint32_t parity) {
    asm volatile(
        "{\n\t.reg .pred P;\n\t"
        "WL_%=:\n\t"
        "mbarrier.try_wait.parity.shared.b64 P, [%0], %1;\n\t"
        "@!P bra WL_%=;\n\t}"
        :: "r"(mbar), "r"(parity) : "memory");
}

#if HAS_TCGEN05
#define LDTM_X32(r, addr)                                                        \
    asm volatile(                                                                \
        "tcgen05.ld.sync.aligned.32x32b.x32.b32 "                                \
        "{%0, %1, %2, %3, %4, %5, %6, %7, "                                      \
        " %8, %9, %10, %11, %12, %13, %14, %15, "                                \
        " %16, %17, %18, %19, %20, %21, %22, %23, "                              \
        " %24, %25, %26, %27, %28, %29, %30, %31}, [%32];"                       \
        : "=r"((r)[0]),  "=r"((r)[1]),  "=r"((r)[2]),  "=r"((r)[3]),             \
          "=r"((r)[4]),  "=r"((r)[5]),  "=r"((r)[6]),  "=r"((r)[7]),             \
          "=r"((r)[8]),  "=r"((r)[9]),  "=r"((r)[10]), "=r"((r)[11]),            \
          "=r"((r)[12]), "=r"((r)[13]), "=r"((r)[14]), "=r"((r)[15]),            \
          "=r"((r)[16]), "=r"((r)[17]), "=r"((r)[18]), "=r"((r)[19]),            \
          "=r"((r)[20]), "=r"((r)[21]), "=r"((r)[22]), "=r"((r)[23]),            \
          "=r"((r)[24]), "=r"((r)[25]), "=r"((r)[26]), "=r"((r)[27]),            \
          "=r"((r)[28]), "=r"((r)[29]), "=r"((r)[30]), "=r"((r)[31])             \
        : "r"(addr))
#endif

// fallback packed-element loaders (compute_103 PTX stage / JIT insurance only)
__device__ __forceinline__ float ld_packA(const float* Ab, int band, int lr, int k) {
    int slab = k >> 5, kk = k & 31;
    size_t base = ((size_t)band * KSLABS + slab) * 8192;
    uint32_t off = swz128((uint32_t)lr * 128 + (uint32_t)kk * 4) >> 2;
    return Ab[base + off] + Ab[base + 4096 + off];
}
__device__ __forceinline__ float ld_packB(const float* Bb, int band, int lr, int k) {
    int slab = k >> 5, kk = k & 31;
    size_t base = ((size_t)band * KSLABS + slab) * 16384;
    uint32_t off = swz128((uint32_t)lr * 128 + (uint32_t)kk * 4) >> 2;
    return Bb[base + off] + Bb[base + 8192 + off];
}

// grid: (Ncols/256, Mrows/128), 128 threads
__global__ __launch_bounds__(128, 1) void k_gemm_tc(
    const float* __restrict__ Ab, const float* __restrict__ Bb, float* __restrict__ C,
    const float* __restrict__ logt_p, const float* __restrict__ bias_p)
{
#if HAS_TCGEN05
    extern __shared__ float dynraw[];
    __shared__ uint32_t s_tmem;
    __shared__ __align__(8) uint64_t s_mbar[4];   // full0 full1 empty0 empty1

    uint32_t rawb  = smem_u32(dynraw);
    uint32_t sbase = (rawb + 1023u) & ~1023u;     // 1024-align for SW128 descriptors
    float*   dyns  = dynraw + ((sbase - rawb) >> 2);
    uint32_t mb    = smem_u32(s_mbar);
    int tid = threadIdx.x, wid = tid >> 5, lid = tid & 31;

    if (wid == 0) {
        asm volatile("tcgen05.alloc.cta_group::1.sync.aligned.shared::cta.b32 [%0], %1;"
                     :: "r"(smem_u32(&s_tmem)), "r"(256u) : "memory");
    }
    if (tid == 0) {
        for (int i = 0; i < 4; i++) mbar_init(mb + i * 8, 1);
    }
    __syncthreads();
    uint32_t tmem = s_tmem;

    if (tid == 0) {
        const char* asrc = (const char*)(Ab + ((size_t)blockIdx.y * KSLABS) * 8192);
        const char* bsrc = (const char*)(Bb + ((size_t)blockIdx.x * KSLABS) * 16384);

        // slab 0
        mbar_expect(mb + 0, STAGE_BYTES);
        bulk_copy(sbase + 0,     asrc, 32768u, mb + 0);
        bulk_copy(sbase + 32768, bsrc, 65536u, mb + 0);

        uint32_t en = 0;
        for (int s = 0; s < KSLABS; s++) {
            int st = s & 1;
            // prefetch slab s+1
            if (s + 1 < KSLABS) {
                int s1 = s + 1, st1 = s1 & 1, k1 = s1 >> 1;
                uint32_t stb1 = sbase + (uint32_t)st1 * STAGE_BYTES;
                if (s1 >= 2) mbar_wait(mb + 16 + st1 * 8, (uint32_t)((k1 - 1) & 1));
                mbar_expect(mb + st1 * 8, STAGE_BYTES);
                bulk_copy(stb1 + 0,     asrc + (size_t)s1 * 32768, 32768u, mb + st1 * 8);
                bulk_copy(stb1 + 32768, bsrc + (size_t)s1 * 65536, 65536u, mb + st1 * 8);
            }
            // consume slab s
            mbar_wait(mb + st * 8, (uint32_t)((s >> 1) & 1));
            uint32_t stb = sbase + (uint32_t)st * STAGE_BYTES;
            uint64_t dah = mkdesc(stb);
            uint64_t dal = mkdesc(stb + 16384);
            uint64_t dbh = mkdesc(stb + 32768);
            uint64_t dbl = mkdesc(stb + 65536);
#pragma unroll
            for (int ks = 0; ks < 4; ks++) {
                uint64_t o = (uint64_t)(ks * 2);
                mma_tf32(tmem, dah + o, dbh + o, en); en = 1;
                mma_tf32(tmem, dal + o, dbh + o, 1);
                mma_tf32(tmem, dah + o, dbl + o, 1);
            }
            tc_commit(mb + 16 + st * 8);
        }
        // drain: each empty barrier completes phase 7 (parity 1) at its 8th commit
        mbar_wait(mb + 16, 1u);
        mbar_wait(mb + 24, 1u);
    }
    __syncthreads();
    asm volatile("tcgen05.fence::after_thread_sync;" ::: "memory");

    // ---- epilogue: TMEM -> (scale) -> SMEM transpose -> coalesced GMEM ----
    const float t  = expf(*logt_p);
    const float bs = *bias_p;
#pragma unroll 1
    for (int cb = 0; cb < 8; cb++) {
        uint32_t r[32];
        LDTM_X32(r, tmem + cb * 32);
        asm volatile("tcgen05.wait::ld.sync.aligned;" ::: "memory");
        int row = wid * 32 + lid;
#pragma unroll
        for (int j = 0; j < 32; j++) {
            float v = __uint_as_float(r[j]) * t + bs;
            dyns[(cb * 32 + j) * 133 + row] = v;
        }
    }
    __syncthreads();

    size_t gr0 = (size_t)blockIdx.y * 128;
    size_t gc0 = (size_t)blockIdx.x * 256;
#pragma unroll 4
    for (int i = tid; i < 128 * 256; i += 128) {
        int row = i >> 8, col = i & 255;
        C[(gr0 + row) * (size_t)N_COLS + gc0 + col] = dyns[col * 133 + row];
    }

    __syncthreads();
    if (wid == 0) {
        asm volatile("tcgen05.relinquish_alloc_permit.cta_group::1.sync.aligned;");
        asm volatile("tcgen05.dealloc.cta_group::1.sync.aligned.b32 %0, %1;" :: "r"(tmem), "r"(256u));
    }
#else
    // -------- non-tcgen05 fallback (compiles for plain compute_103; only runs if
    // the sm_103a cubin were unavailable). Correct, moderate speed. --------
    extern __shared__ float fsm[];   // 64 x 64 staged B tile (padded)
    const float t  = expf(*logt_p);
    const float bs = *bias_p;
    const int band = blockIdx.y;
    const int r    = threadIdx.x;    // one row per thread (128 rows)
    for (int cc = 0; cc < 4; cc++) { // 64-column chunks
        float acc[64];
#pragma unroll
        for (int j = 0; j < 64; j++) acc[j] = 0.f;
        for (int kt = 0; kt < DIMK; kt += 64) {
            __syncthreads();
            for (int i = threadIdx.x; i < 64 * 64; i += 128) {
                int c = i >> 6, k = i & 63;
                int gcol = blockIdx.x * 256 + cc * 64 + c;
                fsm[c * 65 + k] = ld_packB(Bb, gcol >> 8, gcol & 255, kt + k);
            }
            __syncthreads();
            for (int k = 0; k < 64; k++) {
                float a = ld_packA(Ab, band, r, kt + k);
#pragma unroll
                for (int j = 0; j < 64; j++) acc[j] += a * fsm[j * 65 + k];
            }
        }
        size_t grow = (size_t)band * 128 + r;
        float* crow = C + grow * (size_t)N_COLS + (size_t)blockIdx.x * 256 + cc * 64;
#pragma unroll
        for (int j = 0; j < 64; j++) crow[j] = acc[j] * t + bs;
    }
#endif
}

// ---------------- true-positive losses (fp64) + segment min ----------------
__global__ void k_tploss(const int* __restrict__ key,
                         const float* __restrict__ logt_p, const float* __restrict__ bias_p) {
    int s    = blockIdx.x * (blockDim.x >> 5) + (threadIdx.x >> 5);
    int lane = threadIdx.x & 31;
    if (s >= S_ROWS) return;
    int k = key[s];
    const float4* a = (const float4*)(g_zimg + (size_t)s * DIMK);
    const float4* b = (const float4*)(g_ztxt + (size_t)k * DIMK);
    double acc = 0.0;
#pragma unroll
    for (int c = 0; c < 4; c++) {
        float4 av = a[c * 32 + lane];
        float4 bv = b[c * 32 + lane];
        acc += (double)av.x * bv.x + (double)av.y * bv.y +
               (double)av.z * bv.z + (double)av.w * bv.w;
    }
#pragma unroll
    for (int o = 16; o; o >>= 1) acc += __shfl_xor_sync(0xffffffffu, acc, o);
    if (lane == 0) {
        float t = expf(*logt_p), bs = *bias_p;
        float logit = (float)acc * t + bs;
        float y = -logit;
        float loss = fmaxf(y, 0.f) + log1pf(expf(-fabsf(y)));
        g_loss[s] = loss;
        atomicMin(&g_segmin[k], __float_as_int(loss));
    }
}

__global__ void k_select(const int* __restrict__ key) {
    int s = blockIdx.x * blockDim.x + threadIdx.x;
    if (s >= S_ROWS) return;
    int k = key[s];
    if (__float_as_int(g_loss[s]) == g_segmin[k]) atomicMin(&g_sel[k], s);
}

__global__ void k_writesel(float* __restrict__ outsel) {
    int n = blockIdx.x * blockDim.x + threadIdx.x;
    if (n < N_COLS) {
        int v = g_sel[n];
        outsel[n] = (v < S_ROWS) ? (float)v : -1.0f;
    }
}

// ---------------- final loss reduction ----------------
__global__ void k_losssum(const float* __restrict__ FL) {
    const size_t NN = (size_t)N_COLS * N_COLS;
    size_t idx    = (size_t)blockIdx.x * blockDim.x + threadIdx.x;
    size_t stride = (size_t)gridDim.x * blockDim.x;
    double local = 0.0;
    for (; idx < NN; idx += stride) {
        int i = (int)(idx >> 12);
        int j = (int)(idx & (N_COLS - 1));
        float logit = FL[idx];
        float x = (i == j) ? -logit : logit;
        local += (double)(fmaxf(x, 0.f) + log1pf(expf(-fabsf(x))));
    }
    __shared__ double sm[256];
    sm[threadIdx.x] = local;
    __syncthreads();
    for (int o = 128; o; o >>= 1) {
        if (threadIdx.x < o) sm[threadIdx.x] += sm[threadIdx.x + o];
        __syncthreads();
    }
    if (threadIdx.x == 0) atomicAdd(&g_sum, sm[0]);
}

__global__ void k_writeloss(float* __restrict__ out0) {
    if (threadIdx.x == 0) out0[0] = (float)(g_sum / (double)N_COLS);
}

// ---------------- launcher ----------------
extern "C" void kernel_launch(void* const* d_in, const int* in_sizes, int n_in,
                              void* d_out, int out_size) {
    const float* img  = (const float*)d_in[0];
    const float* txt  = (const float*)d_in[1];
    const int*   key  = (const int*)d_in[2];
    const float* logt = (const float*)d_in[3];
    const float* bias = (const float*)d_in[4];
    float* out = (float*)d_out;

    float* out_sel  = out + 1;
    float* out_zimg = out + 1 + N_COLS;
    float* out_ztxt = out_zimg + (size_t)S_ROWS * DIMK;
    float* out_ap   = out_ztxt + (size_t)N_COLS * DIMK;
    float* out_fl   = out_ap + (size_t)S_ROWS * N_COLS;

    void *p_zimg, *p_ztxt, *p_sel, *p_A1, *p_B, *p_A2;
    cudaGetSymbolAddress(&p_zimg, g_zimg);
    cudaGetSymbolAddress(&p_ztxt, g_ztxt);
    cudaGetSymbolAddress(&p_sel,  g_sel);
    cudaGetSymbolAddress(&p_A1,   g_A1);
    cudaGetSymbolAddress(&p_B,    g_B);
    cudaGetSymbolAddress(&p_A2,   g_A2);

    const int SMEM_DYN = (int)(2 * STAGE_BYTES + 1024);
    cudaFuncSetAttribute(k_gemm_tc, cudaFuncAttributeMaxDynamicSharedMemorySize, SMEM_DYN);

    k_init<<<(N_COLS + 255) / 256, 256>>>();

    k_normalize<<<(S_ROWS * 32 + 255) / 256, 256>>>(img, (float*)p_zimg, out_zimg, S_ROWS);
    k_normalize<<<(N_COLS * 32 + 255) / 256, 256>>>(txt, (float*)p_ztxt, out_ztxt, N_COLS);

    // pack split operands
    k_pack<<<(S_ROWS * 128 + 255) / 256, 256>>>((const float*)p_zimg, (float*)p_A1,
                                                S_ROWS, 7, nullptr);
    k_pack<<<(N_COLS * 128 + 255) / 256, 256>>>((const float*)p_ztxt, (float*)p_B,
                                                N_COLS, 8, nullptr);

    // selection path (independent of GEMM1)
    k_tploss<<<(S_ROWS + 7) / 8, 256>>>(key, logt, bias);
    k_select<<<(S_ROWS + 255) / 256, 256>>>(key);
    k_writesel<<<(N_COLS + 255) / 256, 256>>>(out_sel);

    // all_pairs_logits [S, N] via tcgen05 3xTF32
    {
        dim3 grid(N_COLS / 256, S_ROWS / 128);
        k_gemm_tc<<<grid, 128, SMEM_DYN>>>((const float*)p_A1, (const float*)p_B,
                                           out_ap, logt, bias);
    }

    // gather+split selected rows, then final_logits [N, N]
    k_pack<<<(N_COLS * 128 + 255) / 256, 256>>>((const float*)p_zimg, (float*)p_A2,
                                                N_COLS, 7, (const int*)p_sel);
    {
        dim3 grid(N_COLS / 256, N_COLS / 128);
        k_gemm_tc<<<grid, 128, SMEM_DYN>>>((const float*)p_A2, (const float*)p_B,
                                           out_fl, logt, bias);
    }

    k_losssum<<<2048, 256>>>(out_fl);
    k_writeloss<<<1, 32>>>(out + 0);
}

// round 10
// speedup vs baseline: 3.7707x; 1.1778x over previous
#include <cuda_runtime.h>
#include <math.h>
#include <stdint.h>

#define S_ROWS 16384
#define N_COLS 4096
#define DIMK   512
#define NSLAB  16            // K-32 pipeline slabs (each = 2 K-16 B sub-slabs)
#define STAGE_BYTES 98304u   // A: 2 bands x 16KB + B: 64KB
#define GEMM1_BY (S_ROWS / 256)              // 64
#define GEMM_BY  (GEMM1_BY + N_COLS / 256)   // 80

// ---------------- static device scratch ----------------
static __device__ float  g_zimg[S_ROWS * DIMK];
static __device__ float  g_ztxt[N_COLS * DIMK];
// A packed (hi-only tf32): per (band128, slab32): 128 rows x 128B SW128 = 4096 floats
static __device__ float  g_A1[(size_t)S_ROWS * DIMK];
static __device__ float  g_A2[(size_t)N_COLS * DIMK];
// B packed (hi|lo interleaved in 128B rows): per (band256, slab16): 256 x 128B = 8192 floats
static __device__ float  g_B [(size_t)N_COLS * 2 * DIMK];
static __device__ float  g_loss[S_ROWS];
static __device__ int    g_segmin[N_COLS];
static __device__ int    g_sel[N_COLS];
static __device__ double g_sum;

// ---------------- helpers ----------------
__device__ __forceinline__ uint32_t swz128(uint32_t o) { return o ^ ((o >> 3) & 0x70); }

__device__ __forceinline__ uint32_t smem_u32(const void* p) {
    uint32_t a;
    asm("{ .reg .u64 t; cvta.to.shared.u64 t, %1; cvt.u32.u64 %0, t; }" : "=r"(a) : "l"(p));
    return a;
}
__device__ __forceinline__ float tf32hi(float x) {
    uint32_t hb; asm("cvt.rna.tf32.f32 %0, %1;" : "=r"(hb) : "f"(x));
    return __uint_as_float(hb);
}
__device__ __forceinline__ void tf32split(float x, float& h, float& l) {
    h = tf32hi(x);
    l = tf32hi(x - h);
}

// ---------------- init ----------------
__global__ void k_init() {
    int i = blockIdx.x * blockDim.x + threadIdx.x;
    if (i < N_COLS) { g_segmin[i] = 0x7F800000; g_sel[i] = S_ROWS; }
    if (i == 0) g_sum = 0.0;
}

// ---------------- fused normalize + pack ----------------
// mode 0 (A/img): hi-only, band128/slab32 blocks (4096 floats each)
// mode 1 (B/txt): hi+lo in 128B rows, band256/slab16 blocks (8192 floats each)
__global__ void k_normpack(const float* __restrict__ in, float* __restrict__ aligned,
                           float* __restrict__ outreg, float* __restrict__ packed,
                           int rows, int mode) {
    int w    = (blockIdx.x * blockDim.x + threadIdx.x) >> 5;
    int lane = threadIdx.x & 31;
    if (w >= rows) return;
    const float4* src = (const float4*)(in + (size_t)w * DIMK);
    float4 v[4];
    float ss = 0.f;
#pragma unroll
    for (int c = 0; c < 4; c++) {
        v[c] = src[c * 32 + lane];
        ss += v[c].x * v[c].x + v[c].y * v[c].y + v[c].z * v[c].z + v[c].w * v[c].w;
    }
#pragma unroll
    for (int o = 16; o; o >>= 1) ss += __shfl_xor_sync(0xffffffffu, ss, o);
    float scale = 1.0f / (sqrtf(ss) + 1e-12f);
    float4* dst = (float4*)(aligned + (size_t)w * DIMK);
    float*  dr  = outreg + (size_t)w * DIMK;
#pragma unroll
    for (int c = 0; c < 4; c++) {
        float4 o4 = make_float4(v[c].x * scale, v[c].y * scale, v[c].z * scale, v[c].w * scale);
        dst[c * 32 + lane] = o4;
        int q = c * 32 + lane;
        int base4 = q * 4;
        dr[base4 + 0] = o4.x; dr[base4 + 1] = o4.y; dr[base4 + 2] = o4.z; dr[base4 + 3] = o4.w;
        if (mode == 0) {
            int slab = q >> 3, kq = q & 7;
            size_t base = ((size_t)(w >> 7) * 16 + slab) * 4096;
            uint32_t off = swz128((uint32_t)(w & 127) * 128 + (uint32_t)kq * 16) >> 2;
            float4 h4 = make_float4(tf32hi(o4.x), tf32hi(o4.y), tf32hi(o4.z), tf32hi(o4.w));
            *(float4*)(packed + base + off) = h4;
        } else {
            int slab = q >> 2, kq = q & 3;
            size_t base = ((size_t)(w >> 8) * 32 + slab) * 8192;
            uint32_t offh = swz128((uint32_t)(w & 255) * 128 + (uint32_t)kq * 16) >> 2;
            uint32_t offl = swz128((uint32_t)(w & 255) * 128 + 64 + (uint32_t)kq * 16) >> 2;
            float4 h4, l4;
            tf32split(o4.x, h4.x, l4.x); tf32split(o4.y, h4.y, l4.y);
            tf32split(o4.z, h4.z, l4.z); tf32split(o4.w, h4.w, l4.w);
            *(float4*)(packed + base + offh) = h4;
            *(float4*)(packed + base + offl) = l4;
        }
    }
}

// ---------------- pack A2 (gathered selected rows, hi-only) ----------------
__global__ void k_packA2(const float* __restrict__ src, float* __restrict__ dst,
                         const int* __restrict__ gather) {
    int idx = blockIdx.x * blockDim.x + threadIdx.x;  // one float4 per thread
    if (idx >= N_COLS * 128) return;
    int row = idx >> 7, q = idx & 127;
    int g = gather[row];
    float4 v = (g >= S_ROWS) ? make_float4(0.f, 0.f, 0.f, 0.f)
                             : ((const float4*)(src + (size_t)g * DIMK))[q];
    float4 h4 = make_float4(tf32hi(v.x), tf32hi(v.y), tf32hi(v.z), tf32hi(v.w));
    int slab = q >> 3, kq = q & 7;
    size_t base = ((size_t)(row >> 7) * 16 + slab) * 4096;
    uint32_t off = swz128((uint32_t)(row & 127) * 128 + (uint32_t)kq * 16) >> 2;
    *(float4*)(dst + base + off) = h4;
}

// ---------------- tcgen05 TF32 GEMM, tile M256 x N256 ----------------
// idesc: dtype F32, atype/btype TF32, N=256, M=128
static constexpr uint32_t IDESC_TF32 =
    (1u << 4) | (2u << 7) | (2u << 10) | ((256u >> 3) << 17) | ((128u >> 4) << 24);

static constexpr uint64_t DESC_BASE_SW128 =
    (uint64_t(2) << 61) | (uint64_t(1) << 46) | (uint64_t(64) << 32) | (uint64_t(1) << 16);
__device__ __forceinline__ uint64_t mkdesc(uint32_t smem_addr) {
    return DESC_BASE_SW128 | ((uint64_t)(smem_addr >> 4) & 0x3FFF);
}

#if defined(__CUDA_ARCH_FEAT_SM103_ALL) || defined(__CUDA_ARCH_FEAT_SM100_ALL)
#define HAS_TCGEN05 1
#else
#define HAS_TCGEN05 0
#endif

#if HAS_TCGEN05
__device__ __forceinline__ void mma_tf32(uint32_t d, uint64_t ad, uint64_t bd, uint32_t en) {
    asm volatile(
        "{\n\t.reg .pred p;\n\t"
        "setp.ne.u32 p, %4, 0;\n\t"
        "tcgen05.mma.cta_group::1.kind::tf32 [%0], %1, %2, %3, {%5, %5, %5, %5}, p;\n\t}"
        :: "r"(d), "l"(ad), "l"(bd), "r"(IDESC_TF32), "r"(en), "r"(0u) : "memory");
}
__device__ __forceinline__ void tc_commit(uint32_t mbar) {
    asm volatile(
        "tcgen05.commit.cta_group::1.mbarrier::arrive::one.shared::cluster.b64 [%0];"
        :: "r"(mbar) : "memory");
}
#endif

__device__ __forceinline__ void bulk_copy(uint32_t dst, const void* src, uint32_t bytes, uint32_t mbar) {
    asm volatile(
        "cp.async.bulk.shared::cluster.global.mbarrier::complete_tx::bytes [%0], [%1], %2, [%3];"
        :: "r"(dst), "l"(src), "r"(bytes), "r"(mbar) : "memory");
}
__device__ __forceinline__ void mbar_init(uint32_t mbar, uint32_t cnt) {
    asm volatile("mbarrier.init.shared.b64 [%0], %1;" :: "r"(mbar), "r"(cnt) : "memory");
}
__device__ __forceinline__ void mbar_expect(uint32_t mbar, uint32_t bytes) {
    asm volatile("mbarrier.arrive.expect_tx.shared.b64 _, [%0], %1;" :: "r"(mbar), "r"(bytes) : "memory");
}
__device__ __forceinline__ void mbar_wait(uint32_t mbar, uint32_t parity) {
    asm volatile(
        "{\n\t.reg .pred P;\n\t"
        "WL_%=:\n\t"
        "mbarrier.try_wait.parity.shared.b64 P, [%0], %1;\n\t"
        "@!P bra WL_%=;\n\t}"
        :: "r"(mbar), "r"(parity) : "memory");
}

#if HAS_TCGEN05
#define LDTM_X32(r, addr)                                                        \
    asm volatile(                                                                \
        "tcgen05.ld.sync.aligned.32x32b.x32.b32 "                                \
        "{%0, %1, %2, %3, %4, %5, %6, %7, "                                      \
        " %8, %9, %10, %11, %12, %13, %14, %15, "                                \
        " %16, %17, %18, %19, %20, %21, %22, %23, "                              \
        " %24, %25, %26, %27, %28, %29, %30, %31}, [%32];"                       \
        : "=r"((r)[0]),  "=r"((r)[1]),  "=r"((r)[2]),  "=r"((r)[3]),             \
          "=r"((r)[4]),  "=r"((r)[5]),  "=r"((r)[6]),  "=r"((r)[7]),             \
          "=r"((r)[8]),  "=r"((r)[9]),  "=r"((r)[10]), "=r"((r)[11]),            \
          "=r"((r)[12]), "=r"((r)[13]), "=r"((r)[14]), "=r"((r)[15]),            \
          "=r"((r)[16]), "=r"((r)[17]), "=r"((r)[18]), "=r"((r)[19]),            \
          "=r"((r)[20]), "=r"((r)[21]), "=r"((r)[22]), "=r"((r)[23]),            \
          "=r"((r)[24]), "=r"((r)[25]), "=r"((r)[26]), "=r"((r)[27]),            \
          "=r"((r)[28]), "=r"((r)[29]), "=r"((r)[30]), "=r"((r)[31])             \
        : "r"(addr))
#endif

// fallback element loaders (compute_103 plain-PTX stage only)
__device__ __forceinline__ float ld_packA(const float* A, int band, int lr, int k) {
    int slab = k >> 5, kk = k & 31;
    size_t base = ((size_t)band * 16 + slab) * 4096;
    uint32_t off = swz128((uint32_t)lr * 128 + (uint32_t)kk * 4) >> 2;
    return A[base + off];
}
__device__ __forceinline__ float ld_packB(const float* B, int band, int lr, int k) {
    int slab = k >> 4, kk = k & 15;
    size_t base = ((size_t)band * 32 + slab) * 8192;
    uint32_t offh = swz128((uint32_t)lr * 128 + (uint32_t)kk * 4) >> 2;
    uint32_t offl = swz128((uint32_t)lr * 128 + 64 + (uint32_t)kk * 4) >> 2;
    return B[base + offh] + B[base + offl];
}

__device__ __forceinline__ float softplusf(float x) {
    return fmaxf(x, 0.f) + log1pf(expf(-fabsf(x)));
}

// combined GEMM: grid (N_COLS/256, GEMM_BY), 128 threads
// by < GEMM1_BY: C1 = all_pairs (A1); else C2 = final_logits (A2) + fused loss sum
__global__ __launch_bounds__(128, 1) void k_gemm_tc(
    const float* __restrict__ A1b, const float* __restrict__ A2b,
    const float* __restrict__ Bb, float* __restrict__ C1, float* __restrict__ C2,
    const float* __restrict__ logt_p, const float* __restrict__ bias_p)
{
    const int  bx   = blockIdx.x;
    const int  by   = blockIdx.y;
    const bool isFL = (by >= GEMM1_BY);
    const int  byl  = isFL ? (by - GEMM1_BY) : by;
    const float* Ab = isFL ? A2b : A1b;
    float*       C  = isFL ? C2 : C1;
    const int tid = threadIdx.x, wid = tid >> 5, lid = tid & 31;

#if HAS_TCGEN05
    extern __shared__ float dynraw[];
    __shared__ uint32_t s_tmem;
    __shared__ __align__(8) uint64_t s_mbar[4];   // full0 full1 empty0 empty1
    __shared__ double s_red[128];

    uint32_t rawb  = smem_u32(dynraw);
    uint32_t sbase = (rawb + 1023u) & ~1023u;
    float*   dyns  = dynraw + ((sbase - rawb) >> 2);
    uint32_t mb    = smem_u32(s_mbar);

    if (wid == 0) {
        asm volatile("tcgen05.alloc.cta_group::1.sync.aligned.shared::cta.b32 [%0], %1;"
                     :: "r"(smem_u32(&s_tmem)), "r"(512u) : "memory");
    }
    if (tid == 0) {
        for (int i = 0; i < 4; i++) mbar_init(mb + i * 8, 1);
    }
    __syncthreads();
    uint32_t tmem = s_tmem;

    if (tid == 0) {
        const char* a0 = (const char*)(Ab + (size_t)(2 * byl)     * 16 * 4096);
        const char* a1 = (const char*)(Ab + (size_t)(2 * byl + 1) * 16 * 4096);
        const char* bs = (const char*)(Bb + (size_t)bx * 32 * 8192);

        // slab 0
        mbar_expect(mb + 0, STAGE_BYTES);
        bulk_copy(sbase + 0,     a0, 16384u, mb + 0);
        bulk_copy(sbase + 16384, a1, 16384u, mb + 0);
        bulk_copy(sbase + 32768, bs, 65536u, mb + 0);

        uint32_t en0 = 0, en1 = 0;
        for (int s = 0; s < NSLAB; s++) {
            int st = s & 1;
            // prefetch slab s+1
            if (s + 1 < NSLAB) {
                int s1 = s + 1, st1 = s1 & 1, k1 = s1 >> 1;
                uint32_t stb1 = sbase + (uint32_t)st1 * STAGE_BYTES;
                if (s1 >= 2) mbar_wait(mb + 16 + st1 * 8, (uint32_t)((k1 - 1) & 1));
                mbar_expect(mb + st1 * 8, STAGE_BYTES);
                bulk_copy(stb1 + 0,     a0 + (size_t)s1 * 16384, 16384u, mb + st1 * 8);
                bulk_copy(stb1 + 16384, a1 + (size_t)s1 * 16384, 16384u, mb + st1 * 8);
                bulk_copy(stb1 + 32768, bs + (size_t)s1 * 65536, 65536u, mb + st1 * 8);
            }
            // consume slab s
            mbar_wait(mb + st * 8, (uint32_t)((s >> 1) & 1));
            uint32_t stb = sbase + (uint32_t)st * STAGE_BYTES;
#pragma unroll
            for (int m = 0; m < 2; m++) {
                uint64_t da = mkdesc(stb + (uint32_t)m * 16384);
                uint32_t dacc = tmem + (uint32_t)m * 256;
                uint32_t en = m ? en1 : en0;
#pragma unroll
                for (int ks = 0; ks < 4; ks++) {
                    uint64_t db = mkdesc(stb + 32768 + (uint32_t)(ks >> 1) * 32768);
                    uint64_t ao = (uint64_t)(2 * ks);
                    uint64_t bo = (uint64_t)(2 * (ks & 1));
                    mma_tf32(dacc, da + ao, db + bo,     en); en = 1;
                    mma_tf32(dacc, da + ao, db + 4 + bo, 1);
                }
                if (m) en1 = 1; else en0 = 1;
            }
            tc_commit(mb + 16 + st * 8);
        }
        // drain (sequential per-barrier phases make parity exact)
        mbar_wait(mb + 16, 1u);
        mbar_wait(mb + 24, 1u);
    }
    __syncthreads();
    asm volatile("tcgen05.fence::after_thread_sync;" ::: "memory");

    // ---- epilogue: TMEM -> scale -> SMEM transpose -> coalesced GMEM (+ fused FL loss) ----
    const float t  = expf(*logt_p);
    const float bsc = *bias_p;
    const size_t gc0 = (size_t)bx * 256;
    float lsum = 0.f;

#pragma unroll 1
    for (int mh = 0; mh < 2; mh++) {
#pragma unroll 1
        for (int cb = 0; cb < 8; cb++) {
            uint32_t r[32];
            LDTM_X32(r, tmem + mh * 256 + cb * 32);
            asm volatile("tcgen05.wait::ld.sync.aligned;" ::: "memory");
            int row = wid * 32 + lid;
#pragma unroll
            for (int j = 0; j < 32; j++) {
                float v = __uint_as_float(r[j]) * t + bsc;
                dyns[(cb * 32 + j) * 133 + row] = v;
            }
        }
        __syncthreads();
        size_t gr0 = (size_t)byl * 256 + (size_t)mh * 128;
#pragma unroll 4
        for (int i = tid; i < 128 * 256; i += 128) {
            int row = i >> 8, col = i & 255;
            float v = dyns[col * 133 + row];
            C[(gr0 + row) * (size_t)N_COLS + gc0 + col] = v;
            if (isFL) {
                float x = ((gr0 + (size_t)row) == (gc0 + (size_t)col)) ? -v : v;
                lsum += softplusf(x);
            }
        }
        __syncthreads();
    }

    if (isFL) {
        s_red[tid] = (double)lsum;
        __syncthreads();
        for (int o = 64; o; o >>= 1) {
            if (tid < o) s_red[tid] += s_red[tid + o];
            __syncthreads();
        }
        if (tid == 0) atomicAdd(&g_sum, s_red[0]);
    }

    __syncthreads();
    if (wid == 0) {
        asm volatile("tcgen05.relinquish_alloc_permit.cta_group::1.sync.aligned;");
        asm volatile("tcgen05.dealloc.cta_group::1.sync.aligned.b32 %0, %1;" :: "r"(tmem), "r"(512u));
    }
#else
    // -------- non-tcgen05 fallback (plain compute_103 PTX stage; correctness only) --------
    extern __shared__ float fsm[];   // 64 x 64 B tile (padded)
    __shared__ double s_red[128];
    const float t  = expf(*logt_p);
    const float bsc = *bias_p;
    float lsum = 0.f;
    for (int mh = 0; mh < 2; mh++) {
        int band = 2 * byl + mh;
        int r    = tid;              // local row
        for (int cc = 0; cc < 4; cc++) {
            float acc[64];
#pragma unroll
            for (int j = 0; j < 64; j++) acc[j] = 0.f;
            for (int kt = 0; kt < DIMK; kt += 64) {
                __syncthreads();
                for (int i = tid; i < 64 * 64; i += 128) {
                    int c = i >> 6, k = i & 63;
                    int gcol = bx * 256 + cc * 64 + c;
                    fsm[c * 65 + k] = ld_packB(Bb, gcol >> 8, gcol & 255, kt + k);
                }
                __syncthreads();
                for (int k = 0; k < 64; k++) {
                    float a = ld_packA(Ab, band, r, kt + k);
#pragma unroll
                    for (int j = 0; j < 64; j++) acc[j] += a * fsm[j * 65 + k];
                }
            }
            size_t grow = (size_t)band * 128 + r;
            float* crow = C + grow * (size_t)N_COLS + (size_t)bx * 256 + cc * 64;
#pragma unroll
            for (int j = 0; j < 64; j++) {
                float v = acc[j] * t + bsc;
                crow[j] = v;
                if (isFL) {
                    size_t gcol = (size_t)bx * 256 + cc * 64 + j;
                    float x = (grow == gcol) ? -v : v;
                    lsum += softplusf(x);
                }
            }
        }
        __syncthreads();
    }
    if (isFL) {
        s_red[tid] = (double)lsum;
        __syncthreads();
        for (int o = 64; o; o >>= 1) {
            if (tid < o) s_red[tid] += s_red[tid + o];
            __syncthreads();
        }
        if (tid == 0) atomicAdd(&g_sum, s_red[0]);
    }
#endif
}

// ---------------- true-positive losses (fp64) + segment min ----------------
__global__ void k_tploss(const int* __restrict__ key,
                         const float* __restrict__ logt_p, const float* __restrict__ bias_p) {
    int s    = blockIdx.x * (blockDim.x >> 5) + (threadIdx.x >> 5);
    int lane = threadIdx.x & 31;
    if (s >= S_ROWS) return;
    int k = key[s];
    const float4* a = (const float4*)(g_zimg + (size_t)s * DIMK);
    const float4* b = (const float4*)(g_ztxt + (size_t)k * DIMK);
    double acc = 0.0;
#pragma unroll
    for (int c = 0; c < 4; c++) {
        float4 av = a[c * 32 + lane];
        float4 bv = b[c * 32 + lane];
        acc += (double)av.x * bv.x + (double)av.y * bv.y +
               (double)av.z * bv.z + (double)av.w * bv.w;
    }
#pragma unroll
    for (int o = 16; o; o >>= 1) acc += __shfl_xor_sync(0xffffffffu, acc, o);
    if (lane == 0) {
        float t = expf(*logt_p), bs = *bias_p;
        float logit = (float)acc * t + bs;
        float loss = softplusf(-logit);
        g_loss[s] = loss;
        atomicMin(&g_segmin[k], __float_as_int(loss));
    }
}

__global__ void k_select(const int* __restrict__ key) {
    int s = blockIdx.x * blockDim.x + threadIdx.x;
    if (s >= S_ROWS) return;
    int k = key[s];
    if (__float_as_int(g_loss[s]) == g_segmin[k]) atomicMin(&g_sel[k], s);
}

__global__ void k_writesel(float* __restrict__ outsel) {
    int n = blockIdx.x * blockDim.x + threadIdx.x;
    if (n < N_COLS) {
        int v = g_sel[n];
        outsel[n] = (v < S_ROWS) ? (float)v : -1.0f;
    }
}

__global__ void k_writeloss(float* __restrict__ out0) {
    if (threadIdx.x == 0) out0[0] = (float)(g_sum / (double)N_COLS);
}

// ---------------- launcher ----------------
extern "C" void kernel_launch(void* const* d_in, const int* in_sizes, int n_in,
                              void* d_out, int out_size) {
    const float* img  = (const float*)d_in[0];
    const float* txt  = (const float*)d_in[1];
    const int*   key  = (const int*)d_in[2];
    const float* logt = (const float*)d_in[3];
    const float* bias = (const float*)d_in[4];
    float* out = (float*)d_out;

    float* out_sel  = out + 1;
    float* out_zimg = out + 1 + N_COLS;
    float* out_ztxt = out_zimg + (size_t)S_ROWS * DIMK;
    float* out_ap   = out_ztxt + (size_t)N_COLS * DIMK;
    float* out_fl   = out_ap + (size_t)S_ROWS * N_COLS;

    void *p_zimg, *p_ztxt, *p_sel, *p_A1, *p_B, *p_A2;
    cudaGetSymbolAddress(&p_zimg, g_zimg);
    cudaGetSymbolAddress(&p_ztxt, g_ztxt);
    cudaGetSymbolAddress(&p_sel,  g_sel);
    cudaGetSymbolAddress(&p_A1,   g_A1);
    cudaGetSymbolAddress(&p_B,    g_B);
    cudaGetSymbolAddress(&p_A2,   g_A2);

    const int SMEM_DYN = (int)(2 * STAGE_BYTES + 1024);   // 197632
    cudaFuncSetAttribute(k_gemm_tc, cudaFuncAttributeMaxDynamicSharedMemorySize, SMEM_DYN);

    k_init<<<(N_COLS + 255) / 256, 256>>>();

    k_normpack<<<(S_ROWS * 32 + 255) / 256, 256>>>(img, (float*)p_zimg, out_zimg,
                                                   (float*)p_A1, S_ROWS, 0);
    k_normpack<<<(N_COLS * 32 + 255) / 256, 256>>>(txt, (float*)p_ztxt, out_ztxt,
                                                   (float*)p_B, N_COLS, 1);

    // selection path
    k_tploss<<<(S_ROWS + 7) / 8, 256>>>(key, logt, bias);
    k_select<<<(S_ROWS + 255) / 256, 256>>>(key);
    k_writesel<<<(N_COLS + 255) / 256, 256>>>(out_sel);

    // gathered A2 (selected rows)
    k_packA2<<<(N_COLS * 128 + 255) / 256, 256>>>((const float*)p_zimg, (float*)p_A2,
                                                  (const int*)p_sel);

    // combined GEMM: all_pairs [S,N] + final_logits [N,N] (+ fused loss sum)
    {
        dim3 grid(N_COLS / 256, GEMM_BY);
        k_gemm_tc<<<grid, 128, SMEM_DYN>>>((const float*)p_A1, (const float*)p_A2,
                                           (const float*)p_B, out_ap, out_fl, logt, bias);
    }

    k_writeloss<<<1, 32>>>(out + 0);
}

// round 11
// speedup vs baseline: 5.0195x; 1.3312x over previous
#include <cuda_runtime.h>
#include <math.h>
#include <stdint.h>

#define S_ROWS 16384
#define N_COLS 4096
#define DIMK   512
#define NSLAB  16            // K-32 pipeline slabs
#define NSTAGE 3
#define STAGE_BYTES 65536u   // A: 2 bands x 16KB + B: 32KB
#define GEMM1_BY (S_ROWS / 256)              // 64
#define GEMM_BY  (GEMM1_BY + N_COLS / 256)   // 80

// ---------------- static device scratch ----------------
static __device__ float  g_zimg[S_ROWS * DIMK];
static __device__ float  g_ztxt[N_COLS * DIMK];
// packed hi-only tf32, pre-swizzled SMEM tile images:
// A: per (band128, slab32): 128 rows x 128B SW128 = 4096 floats
// B: per (band256, slab32): 256 rows x 128B SW128 = 8192 floats
static __device__ float  g_A1[(size_t)S_ROWS * DIMK];
static __device__ float  g_A2[(size_t)N_COLS * DIMK];
static __device__ float  g_B [(size_t)N_COLS * DIMK];
static __device__ float  g_loss[S_ROWS];
static __device__ int    g_segmin[N_COLS];
static __device__ int    g_sel[N_COLS];
static __device__ double g_sum;

// ---------------- helpers ----------------
__device__ __forceinline__ uint32_t swz128(uint32_t o) { return o ^ ((o >> 3) & 0x70); }

__device__ __forceinline__ uint32_t smem_u32(const void* p) {
    uint32_t a;
    asm("{ .reg .u64 t; cvta.to.shared.u64 t, %1; cvt.u32.u64 %0, t; }" : "=r"(a) : "l"(p));
    return a;
}
__device__ __forceinline__ float tf32hi(float x) {
    uint32_t hb; asm("cvt.rna.tf32.f32 %0, %1;" : "=r"(hb) : "f"(x));
    return __uint_as_float(hb);
}
// TwoProdFMA + branchless Neumaier accumulate: (sum, comp) += a*b exactly
__device__ __forceinline__ void dot2_acc(float a, float b, float& sum, float& comp) {
    float p  = a * b;
    float e  = fmaf(a, b, -p);
    float t1 = sum + p;
    float e2 = (fabsf(sum) >= fabsf(p)) ? ((sum - t1) + p) : ((p - t1) + sum);
    sum  = t1;
    comp += e + e2;
}
__device__ __forceinline__ float softplusf(float x) {
    return fmaxf(x, 0.f) + log1pf(expf(-fabsf(x)));
}

// ---------------- init ----------------
__global__ void k_init() {
    int i = blockIdx.x * blockDim.x + threadIdx.x;
    if (i < N_COLS) { g_segmin[i] = 0x7F800000; g_sel[i] = S_ROWS; }
    if (i == 0) g_sum = 0.0;
}

// ---------------- fused normalize + pack (hi-only tf32) ----------------
// mode 0 (A/img): band128 blocks of 4096 floats; mode 1 (B/txt): band256 blocks of 8192 floats
__global__ void k_normpack(const float* __restrict__ in, float* __restrict__ aligned,
                           float* __restrict__ outreg, float* __restrict__ packed,
                           int rows, int mode) {
    int w    = (blockIdx.x * blockDim.x + threadIdx.x) >> 5;
    int lane = threadIdx.x & 31;
    if (w >= rows) return;
    const float4* src = (const float4*)(in + (size_t)w * DIMK);
    float4 v[4];
    float ss = 0.f;
#pragma unroll
    for (int c = 0; c < 4; c++) {
        v[c] = src[c * 32 + lane];
        ss += v[c].x * v[c].x + v[c].y * v[c].y + v[c].z * v[c].z + v[c].w * v[c].w;
    }
#pragma unroll
    for (int o = 16; o; o >>= 1) ss += __shfl_xor_sync(0xffffffffu, ss, o);
    float scale = 1.0f / (sqrtf(ss) + 1e-12f);
    float4* dst = (float4*)(aligned + (size_t)w * DIMK);
    float*  dr  = outreg + (size_t)w * DIMK;
    const int blog = mode ? 8 : 7;
    const int bmask = (1 << blog) - 1;
    const size_t blk = (size_t)(1 << blog) * 32;   // floats per (band,slab) block
#pragma unroll
    for (int c = 0; c < 4; c++) {
        float4 o4 = make_float4(v[c].x * scale, v[c].y * scale, v[c].z * scale, v[c].w * scale);
        dst[c * 32 + lane] = o4;
        int q = c * 32 + lane;
        int base4 = q * 4;
        dr[base4 + 0] = o4.x; dr[base4 + 1] = o4.y; dr[base4 + 2] = o4.z; dr[base4 + 3] = o4.w;
        int slab = q >> 3, kq = q & 7;
        size_t base = ((size_t)(w >> blog) * 16 + slab) * blk;
        uint32_t off = swz128((uint32_t)(w & bmask) * 128 + (uint32_t)kq * 16) >> 2;
        float4 h4 = make_float4(tf32hi(o4.x), tf32hi(o4.y), tf32hi(o4.z), tf32hi(o4.w));
        *(float4*)(packed + base + off) = h4;
    }
}

// ---------------- pack A2 (gathered selected rows, hi-only) ----------------
__global__ void k_packA2(const float* __restrict__ src, float* __restrict__ dst,
                         const int* __restrict__ gather) {
    int idx = blockIdx.x * blockDim.x + threadIdx.x;  // one float4 per thread
    if (idx >= N_COLS * 128) return;
    int row = idx >> 7, q = idx & 127;
    int g = gather[row];
    float4 v = (g >= S_ROWS) ? make_float4(0.f, 0.f, 0.f, 0.f)
                             : ((const float4*)(src + (size_t)g * DIMK))[q];
    float4 h4 = make_float4(tf32hi(v.x), tf32hi(v.y), tf32hi(v.z), tf32hi(v.w));
    int slab = q >> 3, kq = q & 7;
    size_t base = ((size_t)(row >> 7) * 16 + slab) * 4096;
    uint32_t off = swz128((uint32_t)(row & 127) * 128 + (uint32_t)kq * 16) >> 2;
    *(float4*)(dst + base + off) = h4;
}

// ---------------- tcgen05 TF32 GEMM, tile M256 x N256 ----------------
static constexpr uint32_t IDESC_TF32 =
    (1u << 4) | (2u << 7) | (2u << 10) | ((256u >> 3) << 17) | ((128u >> 4) << 24);

static constexpr uint64_t DESC_BASE_SW128 =
    (uint64_t(2) << 61) | (uint64_t(1) << 46) | (uint64_t(64) << 32) | (uint64_t(1) << 16);
__device__ __forceinline__ uint64_t mkdesc(uint32_t smem_addr) {
    return DESC_BASE_SW128 | ((uint64_t)(smem_addr >> 4) & 0x3FFF);
}

#if defined(__CUDA_ARCH_FEAT_SM103_ALL) || defined(__CUDA_ARCH_FEAT_SM100_ALL)
#define HAS_TCGEN05 1
#else
#define HAS_TCGEN05 0
#endif

#if HAS_TCGEN05
__device__ __forceinline__ void mma_tf32(uint32_t d, uint64_t ad, uint64_t bd, uint32_t en) {
    asm volatile(
        "{\n\t.reg .pred p;\n\t"
        "setp.ne.u32 p, %4, 0;\n\t"
        "tcgen05.mma.cta_group::1.kind::tf32 [%0], %1, %2, %3, {%5, %5, %5, %5}, p;\n\t}"
        :: "r"(d), "l"(ad), "l"(bd), "r"(IDESC_TF32), "r"(en), "r"(0u) : "memory");
}
__device__ __forceinline__ void tc_commit(uint32_t mbar) {
    asm volatile(
        "tcgen05.commit.cta_group::1.mbarrier::arrive::one.shared::cluster.b64 [%0];"
        :: "r"(mbar) : "memory");
}
#endif

__device__ __forceinline__ void bulk_copy(uint32_t dst, const void* src, uint32_t bytes, uint32_t mbar) {
    asm volatile(
        "cp.async.bulk.shared::cluster.global.mbarrier::complete_tx::bytes [%0], [%1], %2, [%3];"
        :: "r"(dst), "l"(src), "r"(bytes), "r"(mbar) : "memory");
}
__device__ __forceinline__ void mbar_init(uint32_t mbar, uint32_t cnt) {
    asm volatile("mbarrier.init.shared.b64 [%0], %1;" :: "r"(mbar), "r"(cnt) : "memory");
}
__device__ __forceinline__ void mbar_expect(uint32_t mbar, uint32_t bytes) {
    asm volatile("mbarrier.arrive.expect_tx.shared.b64 _, [%0], %1;" :: "r"(mbar), "r"(bytes) : "memory");
}
__device__ __forceinline__ void mbar_wait(uint32_t mbar, uint32_t parity) {
    asm volatile(
        "{\n\t.reg .pred P;\n\t"
        "WL_%=:\n\t"
        "mbarrier.try_wait.parity.shared.b64 P, [%0], %1;\n\t"
        "@!P bra WL_%=;\n\t}"
        :: "r"(mbar), "r"(parity) : "memory");
}

#if HAS_TCGEN05
#define LDTM_X32(r, addr)                                                        \
    asm volatile(                                                                \
        "tcgen05.ld.sync.aligned.32x32b.x32.b32 "                                \
        "{%0, %1, %2, %3, %4, %5, %6, %7, "                                      \
        " %8, %9, %10, %11, %12, %13, %14, %15, "                                \
        " %16, %17, %18, %19, %20, %21, %22, %23, "                              \
        " %24, %25, %26, %27, %28, %29, %30, %31}, [%32];"                       \
        : "=r"((r)[0]),  "=r"((r)[1]),  "=r"((r)[2]),  "=r"((r)[3]),             \
          "=r"((r)[4]),  "=r"((r)[5]),  "=r"((r)[6]),  "=r"((r)[7]),             \
          "=r"((r)[8]),  "=r"((r)[9]),  "=r"((r)[10]), "=r"((r)[11]),            \
          "=r"((r)[12]), "=r"((r)[13]), "=r"((r)[14]), "=r"((r)[15]),            \
          "=r"((r)[16]), "=r"((r)[17]), "=r"((r)[18]), "=r"((r)[19]),            \
          "=r"((r)[20]), "=r"((r)[21]), "=r"((r)[22]), "=r"((r)[23]),            \
          "=r"((r)[24]), "=r"((r)[25]), "=r"((r)[26]), "=r"((r)[27]),            \
          "=r"((r)[28]), "=r"((r)[29]), "=r"((r)[30]), "=r"((r)[31])             \
        : "r"(addr))
#endif

// fallback element loaders (compute_103 plain-PTX stage only)
__device__ __forceinline__ float ld_packA(const float* A, int band, int lr, int k) {
    int slab = k >> 5, kk = k & 31;
    size_t base = ((size_t)band * 16 + slab) * 4096;
    uint32_t off = swz128((uint32_t)lr * 128 + (uint32_t)kk * 4) >> 2;
    return A[base + off];
}
__device__ __forceinline__ float ld_packB(const float* B, int band, int lr, int k) {
    int slab = k >> 5, kk = k & 31;
    size_t base = ((size_t)band * 16 + slab) * 8192;
    uint32_t off = swz128((uint32_t)lr * 128 + (uint32_t)kk * 4) >> 2;
    return B[base + off];
}

// combined GEMM: grid (N_COLS/256, GEMM_BY), 128 threads
__global__ __launch_bounds__(128, 1) void k_gemm_tc(
    const float* __restrict__ A1b, const float* __restrict__ A2b,
    const float* __restrict__ Bb, float* __restrict__ C1, float* __restrict__ C2,
    const float* __restrict__ logt_p, const float* __restrict__ bias_p)
{
    const int  bx   = blockIdx.x;
    const int  by   = blockIdx.y;
    const bool isFL = (by >= GEMM1_BY);
    const int  byl  = isFL ? (by - GEMM1_BY) : by;
    const float* Ab = isFL ? A2b : A1b;
    float*       C  = isFL ? C2 : C1;
    const int tid = threadIdx.x, wid = tid >> 5, lid = tid & 31;

#if HAS_TCGEN05
    extern __shared__ float dynraw[];
    __shared__ uint32_t s_tmem;
    __shared__ __align__(8) uint64_t s_mbar[6];   // full[0..2] empty[0..2]
    __shared__ double s_red[128];

    uint32_t rawb  = smem_u32(dynraw);
    uint32_t sbase = (rawb + 1023u) & ~1023u;
    float*   dyns  = dynraw + ((sbase - rawb) >> 2);
    uint32_t mb    = smem_u32(s_mbar);

    if (wid == 0) {
        asm volatile("tcgen05.alloc.cta_group::1.sync.aligned.shared::cta.b32 [%0], %1;"
                     :: "r"(smem_u32(&s_tmem)), "r"(512u) : "memory");
    }
    if (tid == 0) {
        for (int i = 0; i < 6; i++) mbar_init(mb + i * 8, 1);
    }
    __syncthreads();
    uint32_t tmem = s_tmem;

    if (tid == 0) {
        const char* a0 = (const char*)(Ab + (size_t)(2 * byl)     * 16 * 4096);
        const char* a1 = (const char*)(Ab + (size_t)(2 * byl + 1) * 16 * 4096);
        const char* bs = (const char*)(Bb + (size_t)bx * 16 * 8192);

        // prologue: slabs 0, 1
#pragma unroll
        for (int sp = 0; sp < 2; sp++) {
            uint32_t stb = sbase + (uint32_t)sp * STAGE_BYTES;
            mbar_expect(mb + sp * 8, STAGE_BYTES);
            bulk_copy(stb + 0,     a0 + (size_t)sp * 16384, 16384u, mb + sp * 8);
            bulk_copy(stb + 16384, a1 + (size_t)sp * 16384, 16384u, mb + sp * 8);
            bulk_copy(stb + 32768, bs + (size_t)sp * 32768, 32768u, mb + sp * 8);
        }

        uint32_t en0 = 0, en1 = 0;
        for (int s = 0; s < NSLAB; s++) {
            int st = s % 3;
            // prefetch slab s+2
            if (s + 2 < NSLAB) {
                int s2 = s + 2, st2 = s2 % 3, k2 = s2 / 3;
                uint32_t stb2 = sbase + (uint32_t)st2 * STAGE_BYTES;
                if (s2 >= 3) mbar_wait(mb + 24 + st2 * 8, (uint32_t)((k2 - 1) & 1));
                mbar_expect(mb + st2 * 8, STAGE_BYTES);
                bulk_copy(stb2 + 0,     a0 + (size_t)s2 * 16384, 16384u, mb + st2 * 8);
                bulk_copy(stb2 + 16384, a1 + (size_t)s2 * 16384, 16384u, mb + st2 * 8);
                bulk_copy(stb2 + 32768, bs + (size_t)s2 * 32768, 32768u, mb + st2 * 8);
            }
            // consume slab s
            mbar_wait(mb + st * 8, (uint32_t)((s / 3) & 1));
            uint32_t stb = sbase + (uint32_t)st * STAGE_BYTES;
            uint64_t db = mkdesc(stb + 32768);
#pragma unroll
            for (int m = 0; m < 2; m++) {
                uint64_t da = mkdesc(stb + (uint32_t)m * 16384);
                uint32_t dacc = tmem + (uint32_t)m * 256;
                uint32_t en = m ? en1 : en0;
#pragma unroll
                for (int ks = 0; ks < 4; ks++) {
                    uint64_t o = (uint64_t)(2 * ks);
                    mma_tf32(dacc, da + o, db + o, en); en = 1;
                }
                if (m) en1 = 1; else en0 = 1;
            }
            tc_commit(mb + 24 + st * 8);
        }
        // drain: last commits per stage — stage0 phase5(p1), stage1 phase4(p0), stage2 phase4(p0)
        mbar_wait(mb + 24,      1u);
        mbar_wait(mb + 24 + 8,  0u);
        mbar_wait(mb + 24 + 16, 0u);
    }
    __syncthreads();
    asm volatile("tcgen05.fence::after_thread_sync;" ::: "memory");

    // ---- epilogue: TMEM -> scale -> SMEM transpose -> coalesced GMEM (+ fused FL loss) ----
    const float t  = expf(*logt_p);
    const float bsc = *bias_p;
    const size_t gc0 = (size_t)bx * 256;
    float lsum = 0.f;

#pragma unroll 1
    for (int mh = 0; mh < 2; mh++) {
#pragma unroll 1
        for (int cb = 0; cb < 8; cb++) {
            uint32_t r[32];
            LDTM_X32(r, tmem + mh * 256 + cb * 32);
            asm volatile("tcgen05.wait::ld.sync.aligned;" ::: "memory");
            int row = wid * 32 + lid;
#pragma unroll
            for (int j = 0; j < 32; j++) {
                float v = __uint_as_float(r[j]) * t + bsc;
                dyns[(cb * 32 + j) * 133 + row] = v;
            }
        }
        __syncthreads();
        size_t gr0 = (size_t)byl * 256 + (size_t)mh * 128;
#pragma unroll 4
        for (int i = tid; i < 128 * 256; i += 128) {
            int row = i >> 8, col = i & 255;
            float v = dyns[col * 133 + row];
            C[(gr0 + row) * (size_t)N_COLS + gc0 + col] = v;
            if (isFL) {
                float x = ((gr0 + (size_t)row) == (gc0 + (size_t)col)) ? -v : v;
                lsum += softplusf(x);
            }
        }
        __syncthreads();
    }

    if (isFL) {
        s_red[tid] = (double)lsum;
        __syncthreads();
        for (int o = 64; o; o >>= 1) {
            if (tid < o) s_red[tid] += s_red[tid + o];
            __syncthreads();
        }
        if (tid == 0) atomicAdd(&g_sum, s_red[0]);
    }

    __syncthreads();
    if (wid == 0) {
        asm volatile("tcgen05.relinquish_alloc_permit.cta_group::1.sync.aligned;");
        asm volatile("tcgen05.dealloc.cta_group::1.sync.aligned.b32 %0, %1;" :: "r"(tmem), "r"(512u));
    }
#else
    // -------- non-tcgen05 fallback (plain compute_103 PTX stage; correctness only) --------
    extern __shared__ float fsm[];
    __shared__ double s_red[128];
    const float t  = expf(*logt_p);
    const float bsc = *bias_p;
    float lsum = 0.f;
    for (int mh = 0; mh < 2; mh++) {
        int band = 2 * byl + mh;
        int r    = tid;
        for (int cc = 0; cc < 4; cc++) {
            float acc[64];
#pragma unroll
            for (int j = 0; j < 64; j++) acc[j] = 0.f;
            for (int kt = 0; kt < DIMK; kt += 64) {
                __syncthreads();
                for (int i = tid; i < 64 * 64; i += 128) {
                    int c = i >> 6, k = i & 63;
                    int gcol = bx * 256 + cc * 64 + c;
                    fsm[c * 65 + k] = ld_packB(Bb, gcol >> 8, gcol & 255, kt + k);
                }
                __syncthreads();
                for (int k = 0; k < 64; k++) {
                    float a = ld_packA(Ab, band, r, kt + k);
#pragma unroll
                    for (int j = 0; j < 64; j++) acc[j] += a * fsm[j * 65 + k];
                }
            }
            size_t grow = (size_t)band * 128 + r;
            float* crow = C + grow * (size_t)N_COLS + (size_t)bx * 256 + cc * 64;
#pragma unroll
            for (int j = 0; j < 64; j++) {
                float v = acc[j] * t + bsc;
                crow[j] = v;
                if (isFL) {
                    size_t gcol = (size_t)bx * 256 + cc * 64 + j;
                    float x = (grow == gcol) ? -v : v;
                    lsum += softplusf(x);
                }
            }
        }
        __syncthreads();
    }
    if (isFL) {
        s_red[tid] = (double)lsum;
        __syncthreads();
        for (int o = 64; o; o >>= 1) {
            if (tid < o) s_red[tid] += s_red[tid + o];
            __syncthreads();
        }
        if (tid == 0) atomicAdd(&g_sum, s_red[0]);
    }
#endif
}

// ---------------- true-positive losses (compensated fp32) + segment min ----------------
__global__ void k_tploss(const int* __restrict__ key,
                         const float* __restrict__ logt_p, const float* __restrict__ bias_p) {
    int s    = blockIdx.x * (blockDim.x >> 5) + (threadIdx.x >> 5);
    int lane = threadIdx.x & 31;
    if (s >= S_ROWS) return;
    int k = key[s];
    const float4* a = (const float4*)(g_zimg + (size_t)s * DIMK);
    const float4* b = (const float4*)(g_ztxt + (size_t)k * DIMK);
    float sum = 0.f, comp = 0.f;
#pragma unroll
    for (int c = 0; c < 4; c++) {
        float4 av = a[c * 32 + lane];
        float4 bv = b[c * 32 + lane];
        dot2_acc(av.x, bv.x, sum, comp);
        dot2_acc(av.y, bv.y, sum, comp);
        dot2_acc(av.z, bv.z, sum, comp);
        dot2_acc(av.w, bv.w, sum, comp);
    }
    double acc = (double)sum + (double)comp;
#pragma unroll
    for (int o = 16; o; o >>= 1) acc += __shfl_xor_sync(0xffffffffu, acc, o);
    if (lane == 0) {
        float t = expf(*logt_p), bs = *bias_p;
        float logit = (float)acc * t + bs;
        float loss = softplusf(-logit);
        g_loss[s] = loss;
        atomicMin(&g_segmin[k], __float_as_int(loss));
    }
}

__global__ void k_select(const int* __restrict__ key) {
    int s = blockIdx.x * blockDim.x + threadIdx.x;
    if (s >= S_ROWS) return;
    int k = key[s];
    if (__float_as_int(g_loss[s]) == g_segmin[k]) atomicMin(&g_sel[k], s);
}

__global__ void k_writesel(float* __restrict__ outsel) {
    int n = blockIdx.x * blockDim.x + threadIdx.x;
    if (n < N_COLS) {
        int v = g_sel[n];
        outsel[n] = (v < S_ROWS) ? (float)v : -1.0f;
    }
}

__global__ void k_writeloss(float* __restrict__ out0) {
    if (threadIdx.x == 0) out0[0] = (float)(g_sum / (double)N_COLS);
}

// ---------------- launcher ----------------
extern "C" void kernel_launch(void* const* d_in, const int* in_sizes, int n_in,
                              void* d_out, int out_size) {
    const float* img  = (const float*)d_in[0];
    const float* txt  = (const float*)d_in[1];
    const int*   key  = (const int*)d_in[2];
    const float* logt = (const float*)d_in[3];
    const float* bias = (const float*)d_in[4];
    float* out = (float*)d_out;

    float* out_sel  = out + 1;
    float* out_zimg = out + 1 + N_COLS;
    float* out_ztxt = out_zimg + (size_t)S_ROWS * DIMK;
    float* out_ap   = out_ztxt + (size_t)N_COLS * DIMK;
    float* out_fl   = out_ap + (size_t)S_ROWS * N_COLS;

    void *p_zimg, *p_ztxt, *p_sel, *p_A1, *p_B, *p_A2;
    cudaGetSymbolAddress(&p_zimg, g_zimg);
    cudaGetSymbolAddress(&p_ztxt, g_ztxt);
    cudaGetSymbolAddress(&p_sel,  g_sel);
    cudaGetSymbolAddress(&p_A1,   g_A1);
    cudaGetSymbolAddress(&p_B,    g_B);
    cudaGetSymbolAddress(&p_A2,   g_A2);

    const int SMEM_DYN = (int)(NSTAGE * STAGE_BYTES + 1024);   // 197632
    cudaFuncSetAttribute(k_gemm_tc, cudaFuncAttributeMaxDynamicSharedMemorySize, SMEM_DYN);

    k_init<<<(N_COLS + 255) / 256, 256>>>();

    k_normpack<<<(S_ROWS * 32 + 255) / 256, 256>>>(img, (float*)p_zimg, out_zimg,
                                                   (float*)p_A1, S_ROWS, 0);
    k_normpack<<<(N_COLS * 32 + 255) / 256, 256>>>(txt, (float*)p_ztxt, out_ztxt,
                                                   (float*)p_B, N_COLS, 1);

    // selection path
    k_tploss<<<(S_ROWS + 7) / 8, 256>>>(key, logt, bias);
    k_select<<<(S_ROWS + 255) / 256, 256>>>(key);
    k_writesel<<<(N_COLS + 255) / 256, 256>>>(out_sel);

    // gathered A2 (selected rows)
    k_packA2<<<(N_COLS * 128 + 255) / 256, 256>>>((const float*)p_zimg, (float*)p_A2,
                                                  (const int*)p_sel);

    // combined GEMM: all_pairs [S,N] + final_logits [N,N] (+ fused loss sum)
    {
        dim3 grid(N_COLS / 256, GEMM_BY);
        k_gemm_tc<<<grid, 128, SMEM_DYN>>>((const float*)p_A1, (const float*)p_A2,
                                           (const float*)p_B, out_ap, out_fl, logt, bias);
    }

    k_writeloss<<<1, 32>>>(out + 0);
}